// round 7
// baseline (speedup 1.0000x reference)
#include <cuda_runtime.h>

// Problem-fixed sizes (from reference setup_inputs).
#define MAX_N_VARS    1000000
#define MAX_N_CONSTRS 1000000
#define FULLMASK 0xffffffffu

// Scratch (allocs forbidden -> __device__ globals).
__device__ float g_values[MAX_N_VARS];
__device__ float g_ax[MAX_N_CONSTRS];

// ---------------------------------------------------------------------------
// Kernel 1: values = pred*(ub-lb)+lb ; zero ax ; zero out scalar.
// 2 float4 per thread for extra MLP.
// ---------------------------------------------------------------------------
__global__ void prep_kernel(const float4* __restrict__ pred,
                            const float4* __restrict__ lb,
                            const float4* __restrict__ ub,
                            int n_vars4, int n_constrs4, int span,
                            float* __restrict__ out) {
    int t = blockIdx.x * blockDim.x + threadIdx.x;
#pragma unroll
    for (int k = 0; k < 2; k++) {
        int i = t + k * span;
        if (i < n_vars4) {
            float4 p = pred[i];
            float4 l = lb[i];
            float4 u = ub[i];
            float4 v;
            v.x = fmaf(p.x, u.x - l.x, l.x);
            v.y = fmaf(p.y, u.y - l.y, l.y);
            v.z = fmaf(p.z, u.z - l.z, l.z);
            v.w = fmaf(p.w, u.w - l.w, l.w);
            reinterpret_cast<float4*>(g_values)[i] = v;
        }
        if (i < n_constrs4) {
            reinterpret_cast<float4*>(g_ax)[i] = make_float4(0.f, 0.f, 0.f, 0.f);
        }
    }
    if (t == 0) out[0] = 0.0f;
}

// ---------------------------------------------------------------------------
// Kernel 2: segmented scatter-add with warp-level reduce-by-key.
// constr_idx is sorted. Per-thread run-length closes interior runs; head/tail
// partial runs chain across the warp via a segmented shuffle scan, so only
// the lane that closes a row issues the atomic (~1 atomic / row ≈ 1/16 nnz).
// Gathers via __ldcg (L2-only). Streams via plain vector loads.
// ---------------------------------------------------------------------------
#define ITEMS 8

__global__ void __launch_bounds__(256)
spmv_kernel(const float* __restrict__ coeff,
            const int*   __restrict__ cidx,
            const int*   __restrict__ vidx,
            int nnz) {
    long long base = (long long)(blockIdx.x * blockDim.x + threadIdx.x) * ITEMS;
    unsigned lane = threadIdx.x & 31u;
    bool active = base < (long long)nnz;

    int   head_key = -1;
    int   tail_key = -2;   // distinct sentinels so inactive lanes break chains
    float head_acc = 0.f;
    float x        = 0.f;  // tail-run partial (scan value)
    bool  has_b    = false;

    if (active) {
        float c[ITEMS];
        int   ci[ITEMS];
        int count;
        if (base + ITEMS <= nnz) {
            count = ITEMS;
            int vi[ITEMS];
#pragma unroll
            for (int j = 0; j < ITEMS; j += 4) {
                float4 f = *reinterpret_cast<const float4*>(coeff + base + j);
                int4   a = *reinterpret_cast<const int4*>(cidx + base + j);
                int4   b = *reinterpret_cast<const int4*>(vidx + base + j);
                c[j + 0] = f.x; c[j + 1] = f.y; c[j + 2] = f.z; c[j + 3] = f.w;
                ci[j + 0] = a.x; ci[j + 1] = a.y; ci[j + 2] = a.z; ci[j + 3] = a.w;
                vi[j + 0] = b.x; vi[j + 1] = b.y; vi[j + 2] = b.z; vi[j + 3] = b.w;
            }
#pragma unroll
            for (int j = 0; j < ITEMS; j++)
                c[j] = c[j] * __ldcg(g_values + vi[j]);
        } else {
            count = (int)(nnz - base);
            for (int j = 0; j < count; j++) {
                c[j]  = coeff[base + j] * __ldcg(g_values + vidx[base + j]);
                ci[j] = cidx[base + j];
            }
        }

        head_key = ci[0];
        int   cur = ci[0];
        float acc = c[0];
#pragma unroll
        for (int j = 1; j < ITEMS; j++) {
            if (j < count) {
                if (ci[j] == cur) {
                    acc += c[j];
                } else {
                    if (!has_b) { head_acc = acc; has_b = true; }
                    else        atomicAdd(&g_ax[cur], acc);  // interior run
                    cur = ci[j];
                    acc = c[j];
                }
            }
        }
        tail_key = cur;
        x = acc;
    }

    // ---- cross-thread chain (warp segmented inclusive scan) ----
    int  prev_tail = __shfl_up_sync(FULLMASK, tail_key, 1);
    bool brk = (lane == 0) || (prev_tail != head_key);  // chain broken entering lane
    bool F = has_b || brk || !active;                   // segment head at this lane
    float S = x;
#pragma unroll
    for (int d = 1; d < 32; d <<= 1) {
        float sp = __shfl_up_sync(FULLMASK, S, d);
        int   fp = __shfl_up_sync(FULLMASK, (int)F, d);
        if (lane >= d) {
            if (!F) S += sp;
            F = F || (fp != 0);
        }
    }
    float Sprev    = __shfl_up_sync(FULLMASK, S, 1);
    float carry_in = brk ? 0.f : Sprev;

    if (active && has_b)
        atomicAdd(&g_ax[head_key], head_acc + carry_in);

    int  next_head = __shfl_down_sync(FULLMASK, head_key, 1);
    bool flush = (lane == 31) || (tail_key != next_head);
    if (active && flush)
        atomicAdd(&g_ax[tail_key], S);
}

// ---------------------------------------------------------------------------
// Kernel 3: violations + mean reduction (vectorized).
// sense: 1 -> relu(ax-b), 2 -> relu(b-ax), 3 -> |ax-b|, else 0.
// ---------------------------------------------------------------------------
__global__ void loss_kernel(const float4* __restrict__ rhs,
                            const int4*   __restrict__ sense,
                            int n_constrs4, float inv_n,
                            float* __restrict__ out) {
    __shared__ float sdata[32];
    float local = 0.0f;
    int stride = gridDim.x * blockDim.x;
    const float4* ax4 = reinterpret_cast<const float4*>(g_ax);
    for (int i = blockIdx.x * blockDim.x + threadIdx.x; i < n_constrs4; i += stride) {
        float4 a = ax4[i];
        float4 r = rhs[i];
        int4   s = sense[i];
        float d0 = a.x - r.x, d1 = a.y - r.y, d2 = a.z - r.z, d3 = a.w - r.w;
        float v;
        v = (s.x == 1) ? fmaxf(d0, 0.f) : (s.x == 2) ? fmaxf(-d0, 0.f) : (s.x == 3) ? fabsf(d0) : 0.f;
        local += v;
        v = (s.y == 1) ? fmaxf(d1, 0.f) : (s.y == 2) ? fmaxf(-d1, 0.f) : (s.y == 3) ? fabsf(d1) : 0.f;
        local += v;
        v = (s.z == 1) ? fmaxf(d2, 0.f) : (s.z == 2) ? fmaxf(-d2, 0.f) : (s.z == 3) ? fabsf(d2) : 0.f;
        local += v;
        v = (s.w == 1) ? fmaxf(d3, 0.f) : (s.w == 2) ? fmaxf(-d3, 0.f) : (s.w == 3) ? fabsf(d3) : 0.f;
        local += v;
    }
#pragma unroll
    for (int off = 16; off > 0; off >>= 1)
        local += __shfl_down_sync(FULLMASK, local, off);
    int lane = threadIdx.x & 31;
    int wid  = threadIdx.x >> 5;
    if (lane == 0) sdata[wid] = local;
    __syncthreads();
    int nwarps = (blockDim.x + 31) >> 5;
    if (wid == 0) {
        float v = (lane < nwarps) ? sdata[lane] : 0.0f;
#pragma unroll
        for (int off = 16; off > 0; off >>= 1)
            v += __shfl_down_sync(FULLMASK, v, off);
        if (lane == 0) atomicAdd(out, v * inv_n);
    }
}

// Tail-handling loss kernel for n_constrs not divisible by 4 (safety).
__global__ void loss_tail_kernel(const float* __restrict__ rhs,
                                 const int*   __restrict__ sense,
                                 int start, int n_constrs, float inv_n,
                                 float* __restrict__ out) {
    int i = start + blockIdx.x * blockDim.x + threadIdx.x;
    if (i < n_constrs) {
        float diff = g_ax[i] - rhs[i];
        int s = sense[i];
        float v = (s == 1) ? fmaxf(diff, 0.f)
                : (s == 2) ? fmaxf(-diff, 0.f)
                : (s == 3) ? fabsf(diff) : 0.f;
        atomicAdd(out, v * inv_n);
    }
}

// ---------------------------------------------------------------------------
// Launch. Input order: pred, coeff, constr_rhs, var_lb, var_ub,
// constr_idx, var_idx, constr_sense, n_vars, n_constrs.
// ---------------------------------------------------------------------------
extern "C" void kernel_launch(void* const* d_in, const int* in_sizes, int n_in,
                              void* d_out, int out_size) {
    const float* pred  = (const float*)d_in[0];
    const float* coeff = (const float*)d_in[1];
    const float* rhs   = (const float*)d_in[2];
    const float* lb    = (const float*)d_in[3];
    const float* ub    = (const float*)d_in[4];
    const int*   cidx  = (const int*)d_in[5];
    const int*   vidx  = (const int*)d_in[6];
    const int*   sense = (const int*)d_in[7];

    int n_vars    = in_sizes[0];
    int nnz       = in_sizes[1];
    int n_constrs = in_sizes[2];

    float* out = (float*)d_out;
    int threads = 256;

    // prep: vectorized, 2 float4 per thread.
    int n_vars4    = n_vars / 4;
    int n_constrs4 = n_constrs / 4;
    int n_max4 = n_vars4 > n_constrs4 ? n_vars4 : n_constrs4;
    int half = (n_max4 + 1) / 2;
    int blocks_prep = (half + threads - 1) / threads;
    int span = blocks_prep * threads;
    prep_kernel<<<blocks_prep, threads>>>(
        (const float4*)pred, (const float4*)lb, (const float4*)ub,
        n_vars4, n_constrs4, span, out);

    long long n_threads_spmv = ((long long)nnz + ITEMS - 1) / ITEMS;
    int blocks_spmv = (int)((n_threads_spmv + threads - 1) / threads);
    spmv_kernel<<<blocks_spmv, threads>>>(coeff, cidx, vidx, nnz);

    float inv_n = 1.0f / (float)n_constrs;
    int blocks_loss = 1184;  // 8 * 148 SMs
    loss_kernel<<<blocks_loss, threads>>>((const float4*)rhs, (const int4*)sense,
                                          n_constrs4, inv_n, out);
    int tail_start = n_constrs4 * 4;
    if (tail_start < n_constrs) {
        int tail = n_constrs - tail_start;
        loss_tail_kernel<<<(tail + threads - 1) / threads, threads>>>(
            rhs, sense, tail_start, n_constrs, inv_n, out);
    }
}